// round 12
// baseline (speedup 1.0000x reference)
#include <cuda_runtime.h>
#include <math.h>

#define HW     90000
#define NPAIR  45000   // HW/2
#define NQUAD  22500   // HW/4
#define CROP   300
#define NHALF  150
#define DH     32
#define EMB    64
#define CHIN   256
#define PAD    32      // row length (floats) for k/v smem tiles (float4-aligned)

typedef unsigned long long ull;

// ---- packed fp32x2 helpers (sm_100+; ptxas won't auto-fuse, so inline PTX) --
__device__ __forceinline__ ull pack2(float lo, float hi) {
    ull r; asm("mov.b64 %0, {%1, %2};" : "=l"(r) : "f"(lo), "f"(hi)); return r;
}
__device__ __forceinline__ void unpack2(ull v, float& lo, float& hi) {
    asm("mov.b64 {%0, %1}, %2;" : "=f"(lo), "=f"(hi) : "l"(v));
}
__device__ __forceinline__ ull fma2(ull a, ull b, ull c) {
    ull d; asm("fma.rn.f32x2 %0, %1, %2, %3;" : "=l"(d) : "l"(a), "l"(b), "l"(c)); return d;
}
__device__ __forceinline__ ull add2(ull a, ull b) {
    ull d; asm("add.rn.f32x2 %0, %1, %2;" : "=l"(d) : "l"(a), "l"(b)); return d;
}
__device__ __forceinline__ ull mul2(ull a, ull b) {
    ull d; asm("mul.rn.f32x2 %0, %1, %2;" : "=l"(d) : "l"(a), "l"(b)); return d;
}

// ---------------- scratch (static device globals; no runtime allocation) ----
__device__ float g_y1[EMB * HW];   // conv1 out (RAW, pre-BN)
__device__ float g_img[EMB * HW];  // attention scatter output; later z (pre-BN2)
__device__ float g_z[EMB * HW];    // xa staging (fuse2a -> fuse2b)
__device__ float g_bn1[2 * EMB];   // [0:64) scale, [64:128) shift for BN1 fold

// ---------------- conv1: y1[o,hw] = sum_c x[c,hw] * w1[o,c] (raw) ------------
__global__ __launch_bounds__(256, 3) void conv1_kernel(const float* __restrict__ x,
                                                       const float* __restrict__ w1,
                                                       float* __restrict__ y1)
{
    extern __shared__ float sm[];
    float* w_s = sm;  // [256][64] : w_s[c*64+o] = w1[o*256+c]
    int tid = threadIdx.x;
    for (int idx = tid; idx < CHIN * EMB; idx += 256) {
        int c = idx >> 6, o = idx & 63;
        w_s[idx] = w1[o * CHIN + c];
    }
    __syncthreads();

    int og   = tid >> 6;
    int lp   = tid & 63;
    int pair = blockIdx.x * 64 + lp;
    if (pair >= NPAIR) return;

    ull acc[16];
#pragma unroll
    for (int k = 0; k < 16; k++) acc[k] = 0ull;

    const float2* xp = (const float2*)x;
    for (int c0 = 0; c0 < CHIN; c0 += 8) {
        float2 xv[8];
#pragma unroll
        for (int u = 0; u < 8; u++)
            xv[u] = xp[(size_t)(c0 + u) * NPAIR + pair];
#pragma unroll
        for (int u = 0; u < 8; u++) {
            ull xx = pack2(xv[u].x, xv[u].x);
            ull yy = pack2(xv[u].y, xv[u].y);
            const ulonglong2* wr = (const ulonglong2*)(w_s + (c0 + u) * EMB + og * 16);
#pragma unroll
            for (int w4 = 0; w4 < 4; w4++) {
                ulonglong2 wv = wr[w4];
                acc[2*w4+0]   = fma2(xx, wv.x, acc[2*w4+0]);
                acc[2*w4+1]   = fma2(xx, wv.y, acc[2*w4+1]);
                acc[8+2*w4+0] = fma2(yy, wv.x, acc[8+2*w4+0]);
                acc[8+2*w4+1] = fma2(yy, wv.y, acc[8+2*w4+1]);
            }
        }
    }
    float2* yp = (float2*)y1;
#pragma unroll
    for (int k = 0; k < 8; k++) {
        float p0l, p0h, p1l, p1h;
        unpack2(acc[k],     p0l, p0h);
        unpack2(acc[8 + k], p1l, p1h);
        int o = og * 16 + 2 * k;
        yp[(size_t)o       * NPAIR + pair] = make_float2(p0l, p1l);
        yp[(size_t)(o + 1) * NPAIR + pair] = make_float2(p0h, p1h);
    }
}

// ---------------- BN1 stats only: scsh[c]=scale, scsh[64+c]=shift ------------
__global__ __launch_bounds__(1024) void bn_stats_kernel(const float* __restrict__ in,
                                                        const float* __restrict__ gamma,
                                                        const float* __restrict__ beta,
                                                        float* __restrict__ scsh)
{
    int c = blockIdx.x;
    int tid = threadIdx.x;
    const float4* p4 = (const float4*)(in + (size_t)c * HW);

    float s = 0.f, s2 = 0.f;
    for (int i = tid; i < NQUAD; i += 1024) {
        float4 v = p4[i];
        s  += (v.x + v.y) + (v.z + v.w);
        s2 += (v.x*v.x + v.y*v.y) + (v.z*v.z + v.w*v.w);
    }
    __shared__ float rs[32], rs2[32];
#pragma unroll
    for (int off = 16; off; off >>= 1) {
        s  += __shfl_down_sync(0xffffffffu, s, off);
        s2 += __shfl_down_sync(0xffffffffu, s2, off);
    }
    if ((tid & 31) == 0) { rs[tid >> 5] = s; rs2[tid >> 5] = s2; }
    __syncthreads();
    if (tid < 32) {
        float a = rs[tid], a2 = rs2[tid];
#pragma unroll
        for (int off = 16; off; off >>= 1) {
            a  += __shfl_down_sync(0xffffffffu, a, off);
            a2 += __shfl_down_sync(0xffffffffu, a2, off);
        }
        if (tid == 0) {
            const float invn = 1.0f / (float)HW;
            float mean = a * invn;
            float var  = a2 * invn - mean * mean;
            float rstd = rsqrtf(var + 1e-5f);
            float sc = rstd * gamma[c];
            scsh[c]       = sc;
            scsh[EMB + c] = beta[c] - mean * sc;
        }
    }
}

// ---------------- BN2 (stats + apply + relu), one block per channel ----------
__global__ __launch_bounds__(1024) void bn_kernel(const float* __restrict__ in,
                                                  const float* __restrict__ gamma,
                                                  const float* __restrict__ beta,
                                                  float* __restrict__ out)
{
    int c = blockIdx.x;
    int tid = threadIdx.x;
    const float4* p4 = (const float4*)(in + (size_t)c * HW);

    float s = 0.f, s2 = 0.f;
    for (int i = tid; i < NQUAD; i += 1024) {
        float4 v = p4[i];
        s  += (v.x + v.y) + (v.z + v.w);
        s2 += (v.x*v.x + v.y*v.y) + (v.z*v.z + v.w*v.w);
    }
    __shared__ float rs[32], rs2[32];
    __shared__ float sc_s, sh_s;
#pragma unroll
    for (int off = 16; off; off >>= 1) {
        s  += __shfl_down_sync(0xffffffffu, s, off);
        s2 += __shfl_down_sync(0xffffffffu, s2, off);
    }
    if ((tid & 31) == 0) { rs[tid >> 5] = s; rs2[tid >> 5] = s2; }
    __syncthreads();
    if (tid < 32) {
        float a = rs[tid], a2 = rs2[tid];
#pragma unroll
        for (int off = 16; off; off >>= 1) {
            a  += __shfl_down_sync(0xffffffffu, a, off);
            a2 += __shfl_down_sync(0xffffffffu, a2, off);
        }
        if (tid == 0) {
            const float invn = 1.0f / (float)HW;
            float mean = a * invn;
            float var  = a2 * invn - mean * mean;
            float rstd = rsqrtf(var + 1e-5f);
            float sc = rstd * gamma[c];
            sc_s = sc;
            sh_s = beta[c] - mean * sc;
        }
    }
    __syncthreads();
    float sc = sc_s, sh = sh_s;
    float4* q4 = (float4*)(out + (size_t)c * HW);
    for (int i = tid; i < NQUAD; i += 1024) {
        float4 v = p4[i];
        v.x = fmaxf(fmaf(v.x, sc, sh), 0.f);
        v.y = fmaxf(fmaf(v.y, sc, sh), 0.f);
        v.z = fmaxf(fmaf(v.z, sc, sh), 0.f);
        v.w = fmaxf(fmaf(v.w, sc, sh), 0.f);
        q4[i] = v;
    }
}

// ---------------- propagation attention: one block per (h, i) ---------------
// y1 RAW; BN1 folded into gather. Projections as 3 packed c-outer GEMV passes
// (k, v, then q so q2 is the only long-lived accumulator set).
__global__ __launch_bounds__(320, 2) void attn_kernel(const float* __restrict__ y1,
                                                      const float* __restrict__ scsh,
                                                      const float* __restrict__ wq,
                                                      const float* __restrict__ wkv,
                                                      const int* __restrict__ obj,
                                                      const int* __restrict__ bg,
                                                      const int* __restrict__ ri,
                                                      float* __restrict__ img)
{
    extern __shared__ float sm[];
    float* ks    = sm;                    // [300][32]
    float* vs    = ks + CROP * PAD;       // [300][32]
    float* wq_s  = vs + CROP * PAD;       // [32][32]: wq_s[c*32+e]  = wq[e*32+c]
    float* wkv_s = wq_s + 1024;           // [32][64]: wkv_s[c*64+e] = wkv[e*32+c]
    float* scs   = wkv_s + 2048;          // [32] bn1 scale for this head
    float* shs   = scs + 32;              // [32] bn1 shift
    int*   pos_s = (int*)(shs + 32);      // [300]

    int b = blockIdx.x;
    int h = b / CROP;
    int i = b % CROP;
    int tid = threadIdx.x;

    for (int idx = tid; idx < 1024; idx += 320) {
        int e = idx & 31, c = idx >> 5;
        wq_s[c * 32 + e] = wq[e * 32 + c];
    }
    for (int idx = tid; idx < 2048; idx += 320) {
        int e = idx & 63, c = idx >> 6;
        wkv_s[c * 64 + e] = wkv[e * 32 + c];
    }
    if (tid < 32) {
        scs[tid] = scsh[h * DH + tid];
        shs[tid] = scsh[EMB + h * DH + tid];
    }
    for (int j = tid; j < CROP; j += 320) {
        int r = ri[h * (CROP * CROP) + i * CROP + j];
        pos_s[j] = (i < NHALF) ? obj[r] : bg[r];
    }
    __syncthreads();

    ull q2[16];
    if (tid < CROP) {
        float t[DH];
        const float* xb = y1 + (size_t)(h * DH) * HW + pos_s[tid];
#pragma unroll
        for (int c = 0; c < DH; c++)
            t[c] = fmaxf(fmaf(xb[(size_t)c * HW], scs[c], shs[c]), 0.f);

        ull acc[16];
        // ---- k pass ----
#pragma unroll
        for (int e = 0; e < 16; e++) acc[e] = 0ull;
#pragma unroll
        for (int c = 0; c < DH; c++) {
            ull tt = pack2(t[c], t[c]);
            const ulonglong2* wr = (const ulonglong2*)(wkv_s + c * 64);
#pragma unroll
            for (int w = 0; w < 8; w++) {
                ulonglong2 wv = wr[w];
                acc[2*w+0] = fma2(tt, wv.x, acc[2*w+0]);
                acc[2*w+1] = fma2(tt, wv.y, acc[2*w+1]);
            }
        }
        {
            ull* kd = (ull*)(ks + tid * PAD);
#pragma unroll
            for (int e = 0; e < 16; e++) kd[e] = acc[e];
        }
        // ---- v pass ----
#pragma unroll
        for (int e = 0; e < 16; e++) acc[e] = 0ull;
#pragma unroll
        for (int c = 0; c < DH; c++) {
            ull tt = pack2(t[c], t[c]);
            const ulonglong2* wr = (const ulonglong2*)(wkv_s + c * 64 + 32);
#pragma unroll
            for (int w = 0; w < 8; w++) {
                ulonglong2 wv = wr[w];
                acc[2*w+0] = fma2(tt, wv.x, acc[2*w+0]);
                acc[2*w+1] = fma2(tt, wv.y, acc[2*w+1]);
            }
        }
        {
            ull* vd = (ull*)(vs + tid * PAD);
#pragma unroll
            for (int e = 0; e < 16; e++) vd[e] = acc[e];
        }
        // ---- q pass (scale folded) ----
#pragma unroll
        for (int e = 0; e < 16; e++) acc[e] = 0ull;
#pragma unroll
        for (int c = 0; c < DH; c++) {
            ull tt = pack2(t[c], t[c]);
            const ulonglong2* wr = (const ulonglong2*)(wq_s + c * 32);
#pragma unroll
            for (int w = 0; w < 8; w++) {
                ulonglong2 wv = wr[w];
                acc[2*w+0] = fma2(tt, wv.x, acc[2*w+0]);
                acc[2*w+1] = fma2(tt, wv.y, acc[2*w+1]);
            }
        }
        const float scale = 0.17677669529663688110f;  // 32^-0.5
        ull sc2 = pack2(scale, scale);
#pragma unroll
        for (int e = 0; e < 16; e++) q2[e] = mul2(acc[e], sc2);
    }
    __syncthreads();

    if (tid < CROP) {
        float ssum = 0.f;
        ull o2[16];
#pragma unroll
        for (int e = 0; e < 16; e++) o2[e] = 0ull;

#pragma unroll 2
        for (int j = 0; j < CROP; j++) {
            const ulonglong2* kr = (const ulonglong2*)(ks + j * PAD);
            ull d0 = 0ull, d1 = 0ull, d2 = 0ull, d3 = 0ull;
#pragma unroll
            for (int u = 0; u < 4; u++) {
                ulonglong2 ka = kr[2*u], kb = kr[2*u+1];
                d0 = fma2(q2[4*u+0], ka.x, d0);
                d1 = fma2(q2[4*u+1], ka.y, d1);
                d2 = fma2(q2[4*u+2], kb.x, d2);
                d3 = fma2(q2[4*u+3], kb.y, d3);
            }
            ull e_ = add2(add2(d0, d1), add2(d2, d3));
            float lo, hi; unpack2(e_, lo, hi);
            float p = __expf(lo + hi);
            ssum += p;
            ull p2 = pack2(p, p);
            const ulonglong2* vr = (const ulonglong2*)(vs + j * PAD);
#pragma unroll
            for (int u = 0; u < 8; u++) {
                ulonglong2 vv = vr[u];
                o2[2*u+0] = fma2(p2, vv.x, o2[2*u+0]);
                o2[2*u+1] = fma2(p2, vv.y, o2[2*u+1]);
            }
        }
        float inv = 1.0f / ssum;
        float o[DH];
#pragma unroll
        for (int e = 0; e < 16; e++) unpack2(o2[e], o[2*e], o[2*e+1]);

        int mbase = tid * DH;  // m = tid*32 + e
#pragma unroll
        for (int e = 0; e < DH; e++) {
            int mm = mbase + e;
            int d2i = mm / CROP;
            int j2 = mm - d2i * CROP;
            img[(size_t)(h * DH + d2i) * HW + pos_s[j2]] = o[e] * inv;
        }
    }
}

// ------- fuse2a: xa = relu(wo @ img + bo) -> gmem ----------------------------
__global__ __launch_bounds__(256, 3) void fuse2a_kernel(const float* __restrict__ img,
                                                        const float* __restrict__ wo,
                                                        const float* __restrict__ bo,
                                                        float* __restrict__ xa)
{
    extern __shared__ float sm[];
    float* wo_s = sm;             // 4096 : wo_s[c*64+o] = wo[o*64+c]
    float* bo_s = wo_s + 4096;    // 64

    int tid = threadIdx.x;
    for (int idx = tid; idx < 4096; idx += 256) {
        int c = idx >> 6, o = idx & 63;
        wo_s[idx] = wo[o * 64 + c];
    }
    if (tid < 64) bo_s[tid] = bo[tid];
    __syncthreads();

    int og   = tid >> 6;
    int lp   = tid & 63;
    int pair = blockIdx.x * 64 + lp;
    if (pair >= NPAIR) return;

    ull acc[16];
#pragma unroll
    for (int k = 0; k < 16; k++) acc[k] = 0ull;

    const float2* ip = (const float2*)img;
    for (int c0 = 0; c0 < EMB; c0 += 8) {
        float2 iv[8];
#pragma unroll
        for (int u = 0; u < 8; u++)
            iv[u] = ip[(size_t)(c0 + u) * NPAIR + pair];
#pragma unroll
        for (int u = 0; u < 8; u++) {
            ull xx = pack2(iv[u].x, iv[u].x);
            ull yy = pack2(iv[u].y, iv[u].y);
            const ulonglong2* wr = (const ulonglong2*)(wo_s + (c0 + u) * EMB + og * 16);
#pragma unroll
            for (int w4 = 0; w4 < 4; w4++) {
                ulonglong2 wv = wr[w4];
                acc[2*w4+0]   = fma2(xx, wv.x, acc[2*w4+0]);
                acc[2*w4+1]   = fma2(xx, wv.y, acc[2*w4+1]);
                acc[8+2*w4+0] = fma2(yy, wv.x, acc[8+2*w4+0]);
                acc[8+2*w4+1] = fma2(yy, wv.y, acc[8+2*w4+1]);
            }
        }
    }
    float2* xp = (float2*)xa;
#pragma unroll
    for (int k = 0; k < 8; k++) {
        float p0l, p0h, p1l, p1h;
        unpack2(acc[k],     p0l, p0h);
        unpack2(acc[8 + k], p1l, p1h);
        int o = og * 16 + 2 * k;
        float b0 = bo_s[o], b1 = bo_s[o + 1];
        xp[(size_t)o       * NPAIR + pair] = make_float2(fmaxf(p0l + b0, 0.f), fmaxf(p1l + b0, 0.f));
        xp[(size_t)(o + 1) * NPAIR + pair] = make_float2(fmaxf(p0h + b1, 0.f), fmaxf(p1h + b1, 0.f));
    }
}

// ------- fuse2b: z = w2 @ concat(xa, relu(bn1(y1))) --------------------------
__global__ __launch_bounds__(256, 3) void fuse2b_kernel(const float* __restrict__ xa,
                                                        const float* __restrict__ y1,
                                                        const float* __restrict__ scsh,
                                                        const float* __restrict__ w2,
                                                        float* __restrict__ z)
{
    extern __shared__ float sm[];
    float* w2_s = sm;             // 8192 : w2_s[cc*64+o] = w2[o*128+cc]
    float* sc_s = w2_s + 8192;    // 64
    float* sh_s = sc_s + 64;      // 64

    int tid = threadIdx.x;
    for (int idx = tid; idx < 8192; idx += 256) {
        int cc = idx >> 6, o = idx & 63;
        w2_s[idx] = w2[o * 128 + cc];
    }
    if (tid < 128) {
        if (tid < 64) sc_s[tid] = scsh[tid];
        else          sh_s[tid - 64] = scsh[tid];
    }
    __syncthreads();

    int og   = tid >> 6;
    int lp   = tid & 63;
    int pair = blockIdx.x * 64 + lp;
    if (pair >= NPAIR) return;

    ull acc[16];
#pragma unroll
    for (int k = 0; k < 16; k++) acc[k] = 0ull;

    const float2* xap = (const float2*)xa;
    for (int c0 = 0; c0 < EMB; c0 += 8) {   // xa part
        float2 sv[8];
#pragma unroll
        for (int u = 0; u < 8; u++)
            sv[u] = xap[(size_t)(c0 + u) * NPAIR + pair];
#pragma unroll
        for (int u = 0; u < 8; u++) {
            ull xx = pack2(sv[u].x, sv[u].x);
            ull yy = pack2(sv[u].y, sv[u].y);
            const ulonglong2* wr = (const ulonglong2*)(w2_s + (c0 + u) * EMB + og * 16);
#pragma unroll
            for (int w4 = 0; w4 < 4; w4++) {
                ulonglong2 wv = wr[w4];
                acc[2*w4+0]   = fma2(xx, wv.x, acc[2*w4+0]);
                acc[2*w4+1]   = fma2(xx, wv.y, acc[2*w4+1]);
                acc[8+2*w4+0] = fma2(yy, wv.x, acc[8+2*w4+0]);
                acc[8+2*w4+1] = fma2(yy, wv.y, acc[8+2*w4+1]);
            }
        }
    }
    const float2* yp = (const float2*)y1;
    for (int c0 = 0; c0 < EMB; c0 += 8) {   // x1 part with BN1 fold
        float2 sv[8];
#pragma unroll
        for (int u = 0; u < 8; u++)
            sv[u] = yp[(size_t)(c0 + u) * NPAIR + pair];
#pragma unroll
        for (int u = 0; u < 8; u++) {
            int cc = c0 + u;
            float scv = sc_s[cc], shv = sh_s[cc];
            float vx = fmaxf(fmaf(sv[u].x, scv, shv), 0.f);
            float vy = fmaxf(fmaf(sv[u].y, scv, shv), 0.f);
            ull xx = pack2(vx, vx);
            ull yy = pack2(vy, vy);
            const ulonglong2* wr = (const ulonglong2*)(w2_s + (EMB + cc) * EMB + og * 16);
#pragma unroll
            for (int w4 = 0; w4 < 4; w4++) {
                ulonglong2 wv = wr[w4];
                acc[2*w4+0]   = fma2(xx, wv.x, acc[2*w4+0]);
                acc[2*w4+1]   = fma2(xx, wv.y, acc[2*w4+1]);
                acc[8+2*w4+0] = fma2(yy, wv.x, acc[8+2*w4+0]);
                acc[8+2*w4+1] = fma2(yy, wv.y, acc[8+2*w4+1]);
            }
        }
    }
    float2* zp = (float2*)z;
#pragma unroll
    for (int k = 0; k < 8; k++) {
        float p0l, p0h, p1l, p1h;
        unpack2(acc[k],     p0l, p0h);
        unpack2(acc[8 + k], p1l, p1h);
        int o = og * 16 + 2 * k;
        zp[(size_t)o       * NPAIR + pair] = make_float2(p0l, p1l);
        zp[(size_t)(o + 1) * NPAIR + pair] = make_float2(p0h, p1h);
    }
}

// ---------------------------------------------------------------------------
extern "C" void kernel_launch(void* const* d_in, const int* in_sizes, int n_in,
                              void* d_out, int out_size)
{
    const float* x   = (const float*)d_in[0];
    const float* w1  = (const float*)d_in[1];
    const float* g1  = (const float*)d_in[2];
    const float* b1  = (const float*)d_in[3];
    const float* wq  = (const float*)d_in[4];
    const float* wkv = (const float*)d_in[5];
    const float* wo  = (const float*)d_in[6];
    const float* bo  = (const float*)d_in[7];
    const float* w2  = (const float*)d_in[8];
    const float* g2  = (const float*)d_in[9];
    const float* b2  = (const float*)d_in[10];
    const int* obj   = (const int*)d_in[11];
    const int* bg    = (const int*)d_in[12];
    const int* ri    = (const int*)d_in[13];
    float* out = (float*)d_out;

    float *y1p, *imgp, *zp, *bn1p;
    cudaGetSymbolAddress((void**)&y1p, g_y1);
    cudaGetSymbolAddress((void**)&imgp, g_img);
    cudaGetSymbolAddress((void**)&zp, g_z);
    cudaGetSymbolAddress((void**)&bn1p, g_bn1);

    const int CONV1_SMEM  = CHIN * EMB * 4;                                    // 64 KB
    const int ATTN_SMEM   = (2 * CROP * PAD + 1024 + 2048 + 64) * 4 + CROP * 4; // ~90 KB
    const int FUSE2A_SMEM = (4096 + 64) * 4;                                   // ~16 KB
    const int FUSE2B_SMEM = (8192 + 128) * 4;                                  // ~33 KB

    cudaFuncSetAttribute(conv1_kernel,  cudaFuncAttributeMaxDynamicSharedMemorySize, CONV1_SMEM);
    cudaFuncSetAttribute(attn_kernel,   cudaFuncAttributeMaxDynamicSharedMemorySize, ATTN_SMEM);
    cudaFuncSetAttribute(fuse2a_kernel, cudaFuncAttributeMaxDynamicSharedMemorySize, FUSE2A_SMEM);
    cudaFuncSetAttribute(fuse2b_kernel, cudaFuncAttributeMaxDynamicSharedMemorySize, FUSE2B_SMEM);

    int grid_pairs = (NPAIR + 63) / 64;  // 704

    conv1_kernel<<<grid_pairs, 256, CONV1_SMEM>>>(x, w1, y1p);           // y1 raw
    bn_stats_kernel<<<EMB, 1024>>>(y1p, g1, b1, bn1p);                   // scale/shift
    attn_kernel<<<2 * CROP, 320, ATTN_SMEM>>>(y1p, bn1p, wq, wkv, obj, bg, ri, imgp);
    fuse2a_kernel<<<grid_pairs, 256, FUSE2A_SMEM>>>(imgp, wo, bo, zp);   // xa -> g_z
    fuse2b_kernel<<<grid_pairs, 256, FUSE2B_SMEM>>>(zp, y1p, bn1p, w2, imgp); // z -> g_img
    bn_kernel<<<EMB, 1024>>>(imgp, g2, b2, out);
}

// round 13
// speedup vs baseline: 1.0451x; 1.0451x over previous
#include <cuda_runtime.h>
#include <math.h>

#define HW     90000
#define NPAIR  45000   // HW/2
#define NQUAD  22500   // HW/4
#define CROP   300
#define NHALF  150
#define DH     32
#define EMB    64
#define CHIN   256
#define PAD    32      // row length (floats) for k/v smem tiles (float4-aligned)

typedef unsigned long long ull;

// ---- packed fp32x2 helpers (sm_100+; ptxas won't auto-fuse, so inline PTX) --
__device__ __forceinline__ ull pack2(float lo, float hi) {
    ull r; asm("mov.b64 %0, {%1, %2};" : "=l"(r) : "f"(lo), "f"(hi)); return r;
}
__device__ __forceinline__ void unpack2(ull v, float& lo, float& hi) {
    asm("mov.b64 {%0, %1}, %2;" : "=f"(lo), "=f"(hi) : "l"(v));
}
__device__ __forceinline__ ull fma2(ull a, ull b, ull c) {
    ull d; asm("fma.rn.f32x2 %0, %1, %2, %3;" : "=l"(d) : "l"(a), "l"(b), "l"(c)); return d;
}
__device__ __forceinline__ ull add2(ull a, ull b) {
    ull d; asm("add.rn.f32x2 %0, %1, %2;" : "=l"(d) : "l"(a), "l"(b)); return d;
}

// ---------------- scratch (static device globals; no runtime allocation) ----
__device__ float g_y1[EMB * HW];   // conv1 out (RAW, pre-BN)
__device__ float g_img[EMB * HW];  // attention scatter output; later z (pre-BN2)
__device__ float g_z[EMB * HW];    // xa staging (fuse2a -> fuse2b)
__device__ float g_bn1[2 * EMB];   // [0:64) scale, [64:128) shift for BN1 fold

// ---------------- conv1: y1[o,hw] = sum_c x[c,hw] * w1[o,c] (raw) ------------
__global__ __launch_bounds__(256, 3) void conv1_kernel(const float* __restrict__ x,
                                                       const float* __restrict__ w1,
                                                       float* __restrict__ y1)
{
    extern __shared__ float sm[];
    float* w_s = sm;  // [256][64] : w_s[c*64+o] = w1[o*256+c]
    int tid = threadIdx.x;
    for (int idx = tid; idx < CHIN * EMB; idx += 256) {
        int c = idx >> 6, o = idx & 63;
        w_s[idx] = w1[o * CHIN + c];
    }
    __syncthreads();

    int og   = tid >> 6;
    int lp   = tid & 63;
    int pair = blockIdx.x * 64 + lp;
    if (pair >= NPAIR) return;

    ull acc[16];
#pragma unroll
    for (int k = 0; k < 16; k++) acc[k] = 0ull;

    const float2* xp = (const float2*)x;
    for (int c0 = 0; c0 < CHIN; c0 += 8) {
        float2 xv[8];
#pragma unroll
        for (int u = 0; u < 8; u++)
            xv[u] = xp[(size_t)(c0 + u) * NPAIR + pair];
#pragma unroll
        for (int u = 0; u < 8; u++) {
            ull xx = pack2(xv[u].x, xv[u].x);
            ull yy = pack2(xv[u].y, xv[u].y);
            const ulonglong2* wr = (const ulonglong2*)(w_s + (c0 + u) * EMB + og * 16);
#pragma unroll
            for (int w4 = 0; w4 < 4; w4++) {
                ulonglong2 wv = wr[w4];
                acc[2*w4+0]   = fma2(xx, wv.x, acc[2*w4+0]);
                acc[2*w4+1]   = fma2(xx, wv.y, acc[2*w4+1]);
                acc[8+2*w4+0] = fma2(yy, wv.x, acc[8+2*w4+0]);
                acc[8+2*w4+1] = fma2(yy, wv.y, acc[8+2*w4+1]);
            }
        }
    }
    float2* yp = (float2*)y1;
#pragma unroll
    for (int k = 0; k < 8; k++) {
        float p0l, p0h, p1l, p1h;
        unpack2(acc[k],     p0l, p0h);
        unpack2(acc[8 + k], p1l, p1h);
        int o = og * 16 + 2 * k;
        yp[(size_t)o       * NPAIR + pair] = make_float2(p0l, p1l);
        yp[(size_t)(o + 1) * NPAIR + pair] = make_float2(p0h, p1h);
    }
}

// ---------------- BN1 stats only: scsh[c]=scale, scsh[64+c]=shift ------------
__global__ __launch_bounds__(1024) void bn_stats_kernel(const float* __restrict__ in,
                                                        const float* __restrict__ gamma,
                                                        const float* __restrict__ beta,
                                                        float* __restrict__ scsh)
{
    int c = blockIdx.x;
    int tid = threadIdx.x;
    const float4* p4 = (const float4*)(in + (size_t)c * HW);

    float s = 0.f, s2 = 0.f;
    for (int i = tid; i < NQUAD; i += 1024) {
        float4 v = p4[i];
        s  += (v.x + v.y) + (v.z + v.w);
        s2 += (v.x*v.x + v.y*v.y) + (v.z*v.z + v.w*v.w);
    }
    __shared__ float rs[32], rs2[32];
#pragma unroll
    for (int off = 16; off; off >>= 1) {
        s  += __shfl_down_sync(0xffffffffu, s, off);
        s2 += __shfl_down_sync(0xffffffffu, s2, off);
    }
    if ((tid & 31) == 0) { rs[tid >> 5] = s; rs2[tid >> 5] = s2; }
    __syncthreads();
    if (tid < 32) {
        float a = rs[tid], a2 = rs2[tid];
#pragma unroll
        for (int off = 16; off; off >>= 1) {
            a  += __shfl_down_sync(0xffffffffu, a, off);
            a2 += __shfl_down_sync(0xffffffffu, a2, off);
        }
        if (tid == 0) {
            const float invn = 1.0f / (float)HW;
            float mean = a * invn;
            float var  = a2 * invn - mean * mean;
            float rstd = rsqrtf(var + 1e-5f);
            float sc = rstd * gamma[c];
            scsh[c]       = sc;
            scsh[EMB + c] = beta[c] - mean * sc;
        }
    }
}

// ---------------- BN2 (stats + apply + relu), one block per channel ----------
__global__ __launch_bounds__(1024) void bn_kernel(const float* __restrict__ in,
                                                  const float* __restrict__ gamma,
                                                  const float* __restrict__ beta,
                                                  float* __restrict__ out)
{
    int c = blockIdx.x;
    int tid = threadIdx.x;
    const float4* p4 = (const float4*)(in + (size_t)c * HW);

    float s = 0.f, s2 = 0.f;
    for (int i = tid; i < NQUAD; i += 1024) {
        float4 v = p4[i];
        s  += (v.x + v.y) + (v.z + v.w);
        s2 += (v.x*v.x + v.y*v.y) + (v.z*v.z + v.w*v.w);
    }
    __shared__ float rs[32], rs2[32];
    __shared__ float sc_s, sh_s;
#pragma unroll
    for (int off = 16; off; off >>= 1) {
        s  += __shfl_down_sync(0xffffffffu, s, off);
        s2 += __shfl_down_sync(0xffffffffu, s2, off);
    }
    if ((tid & 31) == 0) { rs[tid >> 5] = s; rs2[tid >> 5] = s2; }
    __syncthreads();
    if (tid < 32) {
        float a = rs[tid], a2 = rs2[tid];
#pragma unroll
        for (int off = 16; off; off >>= 1) {
            a  += __shfl_down_sync(0xffffffffu, a, off);
            a2 += __shfl_down_sync(0xffffffffu, a2, off);
        }
        if (tid == 0) {
            const float invn = 1.0f / (float)HW;
            float mean = a * invn;
            float var  = a2 * invn - mean * mean;
            float rstd = rsqrtf(var + 1e-5f);
            float sc = rstd * gamma[c];
            sc_s = sc;
            sh_s = beta[c] - mean * sc;
        }
    }
    __syncthreads();
    float sc = sc_s, sh = sh_s;
    float4* q4 = (float4*)(out + (size_t)c * HW);
    for (int i = tid; i < NQUAD; i += 1024) {
        float4 v = p4[i];
        v.x = fmaxf(fmaf(v.x, sc, sh), 0.f);
        v.y = fmaxf(fmaf(v.y, sc, sh), 0.f);
        v.z = fmaxf(fmaf(v.z, sc, sh), 0.f);
        v.w = fmaxf(fmaf(v.w, sc, sh), 0.f);
        q4[i] = v;
    }
}

// ---------------- propagation attention: one block per (h, i) ---------------
// y1 RAW; BN1 folded into gather. Interleaved scalar q/k/v projection (R11
// form: lowest live-register pressure), packed fp32x2 main loop.
__global__ __launch_bounds__(320, 2) void attn_kernel(const float* __restrict__ y1,
                                                      const float* __restrict__ scsh,
                                                      const float* __restrict__ wq,
                                                      const float* __restrict__ wkv,
                                                      const int* __restrict__ obj,
                                                      const int* __restrict__ bg,
                                                      const int* __restrict__ ri,
                                                      float* __restrict__ img)
{
    extern __shared__ float sm[];
    float* ks    = sm;                    // [300][32]
    float* vs    = ks + CROP * PAD;       // [300][32]
    float* wq_s  = vs + CROP * PAD;       // [32][32]: wq_s[c*32+e]  = wq[e*32+c]
    float* wkv_s = wq_s + 1024;           // [32][64]: wkv_s[c*64+e] = wkv[e*32+c]
    float* scs   = wkv_s + 2048;          // [32] bn1 scale for this head
    float* shs   = scs + 32;              // [32] bn1 shift
    int*   pos_s = (int*)(shs + 32);      // [300]

    int b = blockIdx.x;
    int h = b / CROP;
    int i = b % CROP;
    int tid = threadIdx.x;

    for (int idx = tid; idx < 1024; idx += 320) {
        int e = idx & 31, c = idx >> 5;
        wq_s[c * 32 + e] = wq[e * 32 + c];
    }
    for (int idx = tid; idx < 2048; idx += 320) {
        int e = idx & 63, c = idx >> 6;
        wkv_s[c * 64 + e] = wkv[e * 32 + c];
    }
    if (tid < 32) {
        scs[tid] = scsh[h * DH + tid];
        shs[tid] = scsh[EMB + h * DH + tid];
    }
    for (int j = tid; j < CROP; j += 320) {
        int r = ri[h * (CROP * CROP) + i * CROP + j];
        pos_s[j] = (i < NHALF) ? obj[r] : bg[r];
    }
    __syncthreads();

    ull q2[16];
    if (tid < CROP) {
        float t[DH];
        const float* xb = y1 + (size_t)(h * DH) * HW + pos_s[tid];
#pragma unroll
        for (int c = 0; c < DH; c++)
            t[c] = fmaxf(fmaf(xb[(size_t)c * HW], scs[c], shs[c]), 0.f);

        const float scale = 0.17677669529663688110f;  // 32^-0.5
        float qv[DH];
#pragma unroll
        for (int e = 0; e < DH; e++) {
            float aq = 0.f, ak = 0.f, av = 0.f;
#pragma unroll
            for (int c = 0; c < DH; c++) {
                float tv = t[c];
                aq += tv * wq_s[c * 32 + e];
                ak += tv * wkv_s[c * 64 + e];
                av += tv * wkv_s[c * 64 + 32 + e];
            }
            qv[e] = aq * scale;
            ks[tid * PAD + e] = ak;
            vs[tid * PAD + e] = av;
        }
#pragma unroll
        for (int e = 0; e < 16; e++) q2[e] = pack2(qv[2*e], qv[2*e+1]);
    }
    __syncthreads();

    if (tid < CROP) {
        float ssum = 0.f;
        ull o2[16];
#pragma unroll
        for (int e = 0; e < 16; e++) o2[e] = 0ull;

        const ulonglong2* kbase = (const ulonglong2*)ks;
        const ulonglong2* vbase = (const ulonglong2*)vs;

#pragma unroll 2
        for (int j = 0; j < CROP; j++) {
            const ulonglong2* kr = kbase + j * (PAD / 4);
            ull d0 = 0ull, d1 = 0ull, d2 = 0ull, d3 = 0ull;
#pragma unroll
            for (int u = 0; u < 4; u++) {
                ulonglong2 ka = kr[2*u], kb = kr[2*u+1];
                d0 = fma2(q2[4*u+0], ka.x, d0);
                d1 = fma2(q2[4*u+1], ka.y, d1);
                d2 = fma2(q2[4*u+2], kb.x, d2);
                d3 = fma2(q2[4*u+3], kb.y, d3);
            }
            ull e_ = add2(add2(d0, d1), add2(d2, d3));
            float lo, hi; unpack2(e_, lo, hi);
            float p = __expf(lo + hi);
            ssum += p;
            ull p2 = pack2(p, p);
            const ulonglong2* vr = vbase + j * (PAD / 4);
#pragma unroll
            for (int u = 0; u < 8; u++) {
                ulonglong2 vv = vr[u];
                o2[2*u+0] = fma2(p2, vv.x, o2[2*u+0]);
                o2[2*u+1] = fma2(p2, vv.y, o2[2*u+1]);
            }
        }
        float inv = 1.0f / ssum;
        float o[DH];
#pragma unroll
        for (int e = 0; e < 16; e++) unpack2(o2[e], o[2*e], o[2*e+1]);

        int mbase = tid * DH;  // m = tid*32 + e
#pragma unroll
        for (int e = 0; e < DH; e++) {
            int mm = mbase + e;
            int d2i = mm / CROP;
            int j2 = mm - d2i * CROP;
            img[(size_t)(h * DH + d2i) * HW + pos_s[j2]] = o[e] * inv;
        }
    }
}

// ------- fuse2a: xa = relu(wo @ img + bo) -> gmem ----------------------------
__global__ __launch_bounds__(256, 3) void fuse2a_kernel(const float* __restrict__ img,
                                                        const float* __restrict__ wo,
                                                        const float* __restrict__ bo,
                                                        float* __restrict__ xa)
{
    extern __shared__ float sm[];
    float* wo_s = sm;             // 4096 : wo_s[c*64+o] = wo[o*64+c]
    float* bo_s = wo_s + 4096;    // 64

    int tid = threadIdx.x;
    for (int idx = tid; idx < 4096; idx += 256) {
        int c = idx >> 6, o = idx & 63;
        wo_s[idx] = wo[o * 64 + c];
    }
    if (tid < 64) bo_s[tid] = bo[tid];
    __syncthreads();

    int og   = tid >> 6;
    int lp   = tid & 63;
    int pair = blockIdx.x * 64 + lp;
    if (pair >= NPAIR) return;

    ull acc[16];
#pragma unroll
    for (int k = 0; k < 16; k++) acc[k] = 0ull;

    const float2* ip = (const float2*)img;
    for (int c0 = 0; c0 < EMB; c0 += 8) {
        float2 iv[8];
#pragma unroll
        for (int u = 0; u < 8; u++)
            iv[u] = ip[(size_t)(c0 + u) * NPAIR + pair];
#pragma unroll
        for (int u = 0; u < 8; u++) {
            ull xx = pack2(iv[u].x, iv[u].x);
            ull yy = pack2(iv[u].y, iv[u].y);
            const ulonglong2* wr = (const ulonglong2*)(wo_s + (c0 + u) * EMB + og * 16);
#pragma unroll
            for (int w4 = 0; w4 < 4; w4++) {
                ulonglong2 wv = wr[w4];
                acc[2*w4+0]   = fma2(xx, wv.x, acc[2*w4+0]);
                acc[2*w4+1]   = fma2(xx, wv.y, acc[2*w4+1]);
                acc[8+2*w4+0] = fma2(yy, wv.x, acc[8+2*w4+0]);
                acc[8+2*w4+1] = fma2(yy, wv.y, acc[8+2*w4+1]);
            }
        }
    }
    float2* xp = (float2*)xa;
#pragma unroll
    for (int k = 0; k < 8; k++) {
        float p0l, p0h, p1l, p1h;
        unpack2(acc[k],     p0l, p0h);
        unpack2(acc[8 + k], p1l, p1h);
        int o = og * 16 + 2 * k;
        float b0 = bo_s[o], b1 = bo_s[o + 1];
        xp[(size_t)o       * NPAIR + pair] = make_float2(fmaxf(p0l + b0, 0.f), fmaxf(p1l + b0, 0.f));
        xp[(size_t)(o + 1) * NPAIR + pair] = make_float2(fmaxf(p0h + b1, 0.f), fmaxf(p1h + b1, 0.f));
    }
}

// ------- fuse2b: z = w2 @ concat(xa, relu(bn1(y1))) --------------------------
__global__ __launch_bounds__(256, 3) void fuse2b_kernel(const float* __restrict__ xa,
                                                        const float* __restrict__ y1,
                                                        const float* __restrict__ scsh,
                                                        const float* __restrict__ w2,
                                                        float* __restrict__ z)
{
    extern __shared__ float sm[];
    float* w2_s = sm;             // 8192 : w2_s[cc*64+o] = w2[o*128+cc]
    float* sc_s = w2_s + 8192;    // 64
    float* sh_s = sc_s + 64;      // 64

    int tid = threadIdx.x;
    for (int idx = tid; idx < 8192; idx += 256) {
        int cc = idx >> 6, o = idx & 63;
        w2_s[idx] = w2[o * 128 + cc];
    }
    if (tid < 128) {
        if (tid < 64) sc_s[tid] = scsh[tid];
        else          sh_s[tid - 64] = scsh[tid];
    }
    __syncthreads();

    int og   = tid >> 6;
    int lp   = tid & 63;
    int pair = blockIdx.x * 64 + lp;
    if (pair >= NPAIR) return;

    ull acc[16];
#pragma unroll
    for (int k = 0; k < 16; k++) acc[k] = 0ull;

    const float2* xap = (const float2*)xa;
    for (int c0 = 0; c0 < EMB; c0 += 8) {   // xa part
        float2 sv[8];
#pragma unroll
        for (int u = 0; u < 8; u++)
            sv[u] = xap[(size_t)(c0 + u) * NPAIR + pair];
#pragma unroll
        for (int u = 0; u < 8; u++) {
            ull xx = pack2(sv[u].x, sv[u].x);
            ull yy = pack2(sv[u].y, sv[u].y);
            const ulonglong2* wr = (const ulonglong2*)(w2_s + (c0 + u) * EMB + og * 16);
#pragma unroll
            for (int w4 = 0; w4 < 4; w4++) {
                ulonglong2 wv = wr[w4];
                acc[2*w4+0]   = fma2(xx, wv.x, acc[2*w4+0]);
                acc[2*w4+1]   = fma2(xx, wv.y, acc[2*w4+1]);
                acc[8+2*w4+0] = fma2(yy, wv.x, acc[8+2*w4+0]);
                acc[8+2*w4+1] = fma2(yy, wv.y, acc[8+2*w4+1]);
            }
        }
    }
    const float2* yp = (const float2*)y1;
    for (int c0 = 0; c0 < EMB; c0 += 8) {   // x1 part with BN1 fold
        float2 sv[8];
#pragma unroll
        for (int u = 0; u < 8; u++)
            sv[u] = yp[(size_t)(c0 + u) * NPAIR + pair];
#pragma unroll
        for (int u = 0; u < 8; u++) {
            int cc = c0 + u;
            float scv = sc_s[cc], shv = sh_s[cc];
            float vx = fmaxf(fmaf(sv[u].x, scv, shv), 0.f);
            float vy = fmaxf(fmaf(sv[u].y, scv, shv), 0.f);
            ull xx = pack2(vx, vx);
            ull yy = pack2(vy, vy);
            const ulonglong2* wr = (const ulonglong2*)(w2_s + (EMB + cc) * EMB + og * 16);
#pragma unroll
            for (int w4 = 0; w4 < 4; w4++) {
                ulonglong2 wv = wr[w4];
                acc[2*w4+0]   = fma2(xx, wv.x, acc[2*w4+0]);
                acc[2*w4+1]   = fma2(xx, wv.y, acc[2*w4+1]);
                acc[8+2*w4+0] = fma2(yy, wv.x, acc[8+2*w4+0]);
                acc[8+2*w4+1] = fma2(yy, wv.y, acc[8+2*w4+1]);
            }
        }
    }
    float2* zp = (float2*)z;
#pragma unroll
    for (int k = 0; k < 8; k++) {
        float p0l, p0h, p1l, p1h;
        unpack2(acc[k],     p0l, p0h);
        unpack2(acc[8 + k], p1l, p1h);
        int o = og * 16 + 2 * k;
        zp[(size_t)o       * NPAIR + pair] = make_float2(p0l, p1l);
        zp[(size_t)(o + 1) * NPAIR + pair] = make_float2(p0h, p1h);
    }
}

// ---------------------------------------------------------------------------
extern "C" void kernel_launch(void* const* d_in, const int* in_sizes, int n_in,
                              void* d_out, int out_size)
{
    const float* x   = (const float*)d_in[0];
    const float* w1  = (const float*)d_in[1];
    const float* g1  = (const float*)d_in[2];
    const float* b1  = (const float*)d_in[3];
    const float* wq  = (const float*)d_in[4];
    const float* wkv = (const float*)d_in[5];
    const float* wo  = (const float*)d_in[6];
    const float* bo  = (const float*)d_in[7];
    const float* w2  = (const float*)d_in[8];
    const float* g2  = (const float*)d_in[9];
    const float* b2  = (const float*)d_in[10];
    const int* obj   = (const int*)d_in[11];
    const int* bg    = (const int*)d_in[12];
    const int* ri    = (const int*)d_in[13];
    float* out = (float*)d_out;

    float *y1p, *imgp, *zp, *bn1p;
    cudaGetSymbolAddress((void**)&y1p, g_y1);
    cudaGetSymbolAddress((void**)&imgp, g_img);
    cudaGetSymbolAddress((void**)&zp, g_z);
    cudaGetSymbolAddress((void**)&bn1p, g_bn1);

    const int CONV1_SMEM  = CHIN * EMB * 4;                                    // 64 KB
    const int ATTN_SMEM   = (2 * CROP * PAD + 1024 + 2048 + 64) * 4 + CROP * 4; // ~90 KB
    const int FUSE2A_SMEM = (4096 + 64) * 4;                                   // ~16 KB
    const int FUSE2B_SMEM = (8192 + 128) * 4;                                  // ~33 KB

    cudaFuncSetAttribute(conv1_kernel,  cudaFuncAttributeMaxDynamicSharedMemorySize, CONV1_SMEM);
    cudaFuncSetAttribute(attn_kernel,   cudaFuncAttributeMaxDynamicSharedMemorySize, ATTN_SMEM);
    cudaFuncSetAttribute(fuse2a_kernel, cudaFuncAttributeMaxDynamicSharedMemorySize, FUSE2A_SMEM);
    cudaFuncSetAttribute(fuse2b_kernel, cudaFuncAttributeMaxDynamicSharedMemorySize, FUSE2B_SMEM);

    int grid_pairs = (NPAIR + 63) / 64;  // 704

    conv1_kernel<<<grid_pairs, 256, CONV1_SMEM>>>(x, w1, y1p);           // y1 raw
    bn_stats_kernel<<<EMB, 1024>>>(y1p, g1, b1, bn1p);                   // scale/shift
    attn_kernel<<<2 * CROP, 320, ATTN_SMEM>>>(y1p, bn1p, wq, wkv, obj, bg, ri, imgp);
    fuse2a_kernel<<<grid_pairs, 256, FUSE2A_SMEM>>>(imgp, wo, bo, zp);   // xa -> g_z
    fuse2b_kernel<<<grid_pairs, 256, FUSE2B_SMEM>>>(zp, y1p, bn1p, w2, imgp); // z -> g_img
    bn_kernel<<<EMB, 1024>>>(imgp, g2, b2, out);
}